// round 7
// baseline (speedup 1.0000x reference)
#include <cuda_runtime.h>

// PCEN stack, round 6: occupancy + ILP fix.
// R5 post-mortem: packed f32x2 cut instructions but halved per-thread ILP and
// kept occupancy at 23% -> latency-bound, no speedup. This round: 4 scalar
// FFMA chains (independent, and constexpr coefficients -> FFMA-imm rt=1),
// CH=8 elems/thread, 256 threads/block -> ~40 state regs, 3 blocks/SM,
// 37.5% occupancy. Scan: warp Kogge-Stone (factor q^8) + 8-warp smem fold
// (factor q^256), per-k depth truncation.
//
// Epilogue identities (validated rel_err ~1.2e-6 in earlier rounds):
//   log(EPS)+log1p(M/EPS) = log(M+EPS)
//   M'/delta = exp2(-alpha*lg2(M+EPS) - ld*log2e)
//   (x*M+d)^r - d^r = d^r*(exp2(r*lg2(1 + x*M'/d)) - 1)

static __device__ __forceinline__ float ex2_(float v) {
    float r; asm("ex2.approx.f32 %0, %1;" : "=f"(r) : "f"(v)); return r;
}
static __device__ __forceinline__ float lg2_(float v) {
    float r; asm("lg2.approx.f32 %0, %1;" : "=f"(r) : "f"(v)); return r;
}

// Compile-time power in DOUBLE; flush tiny results to 0 on float conversion.
static constexpr __host__ __device__ double dpow(double b, int n) {
    double r = 1.0;
    for (int i = 0; i < n; ++i) r *= b;
    return r;
}
static constexpr __host__ __device__ float cpf(double v) {
    return (v < 1.0e-37 && v > -1.0e-37) ? 0.0f : (float)v;
}

static constexpr float s0 = 0.015f, s1 = 0.04f, s2 = 0.1f, s3 = 0.25f;
static constexpr float q0 = 1.f - s0, q1 = 1.f - s1, q2 = 1.f - s2, q3 = 1.f - s3;
// warp-scan step factors q^(8*2^j)
static constexpr float P8_0   = cpf(dpow(q0, 8)),   P8_1   = cpf(dpow(q1, 8)),
                       P8_2   = cpf(dpow(q2, 8)),   P8_3   = cpf(dpow(q3, 8));
static constexpr float P16_0  = cpf(dpow(q0, 16)),  P16_1  = cpf(dpow(q1, 16)),
                       P16_2  = cpf(dpow(q2, 16)),  P16_3  = cpf(dpow(q3, 16));
static constexpr float P32_0  = cpf(dpow(q0, 32)),  P32_1  = cpf(dpow(q1, 32)),
                       P32_2  = cpf(dpow(q2, 32)),  P32_3  = cpf(dpow(q3, 32));
static constexpr float P64_0  = cpf(dpow(q0, 64)),  P64_1  = cpf(dpow(q1, 64)),
                       P64_2  = cpf(dpow(q2, 64));
static constexpr float P128_0 = cpf(dpow(q0, 128)), P128_1 = cpf(dpow(q1, 128));
// cross-warp fold factor q^256 (one warp = 32 lanes * 8 elems)
static constexpr float P256_0 = cpf(dpow(q0, 256)), P256_1 = cpf(dpow(q1, 256)),
                       P256_2 = cpf(dpow(q2, 256)), P256_3 = cpf(dpow(q3, 256));

__global__ __launch_bounds__(256, 3)
void pcen_kernel(const float* __restrict__ x,
                 const float* __restrict__ i_sig_alpha,
                 const float* __restrict__ log_delta,
                 const float* __restrict__ i_sig_r,
                 const float* __restrict__ z_ks,
                 float* __restrict__ out,
                 int P, int F)
{
    constexpr int T = 2048, CH = 8, K = 4, NW = 8;
    constexpr unsigned ALL = 0xffffffffu;

    const int row  = blockIdx.x;                 // ((b*P)+p)*F + f
    const int p    = (row / F) % P;
    const int f    = row % F;
    const int base = row * T;
    const int tid  = threadIdx.x;
    const int lane = tid & 31;
    const int w    = tid >> 5;

    // per-lane geometric factors Q8^lane (fwd) / Q8^(31-lane) (bwd), one ex2 each
    const float lf = (float)lane, lb = (float)(31 - lane);
    const float g0 = lg2_(P8_0), g1 = lg2_(P8_1), g2 = lg2_(P8_2), g3 = lg2_(P8_3);
    const float Qlf[K] = { ex2_(lf * g0), ex2_(lf * g1), ex2_(lf * g2), ex2_(lf * g3) };
    const float Qlb[K] = { ex2_(lb * g0), ex2_(lb * g1), ex2_(lb * g2), ex2_(lb * g3) };

    // ---- per-(p,f) scalars ----
    const float alpha  = 1.0f / (1.0f + __expf(-i_sig_alpha[p]));
    const float rr     = 1.0f / (1.0f + __expf(-i_sig_r[p]));
    const float ld     = log_delta[p];
    const float nalpha = -alpha;
    const float c2     = -ld * 1.4426950408889634f;            // -ld*log2e
    const float dr     = ex2_(rr * ld * 1.4426950408889634f);  // delta^r

    float zk0 = z_ks[(p * K + 0) * F + f];
    float zk1 = z_ks[(p * K + 1) * F + f];
    float zk2 = z_ks[(p * K + 2) * F + f];
    float zk3 = z_ks[(p * K + 3) * F + f];
    float zm = fmaxf(fmaxf(zk0, zk1), fmaxf(zk2, zk3));
    float e0 = __expf(zk0 - zm), e1 = __expf(zk1 - zm),
          e2 = __expf(zk2 - zm), e3 = __expf(zk3 - zm);
    const float inv_sum = 1.0f / (e0 + e1 + e2 + e3);
    // w_k * s_k^2 (converts scaled z back to true units inside the mix)
    const float ws[K] = { e0 * inv_sum * s0 * s0, e1 * inv_sum * s1 * s1,
                          e2 * inv_sum * s2 * s2, e3 * inv_sum * s3 * s3 };

    // ---- load x: 8 contiguous floats (2x LDG.128) ----
    float xr[CH];
    const float4* xv = reinterpret_cast<const float4*>(x + base + tid * CH);
#pragma unroll
    for (int j = 0; j < CH / 4; ++j) {
        float4 v = xv[j];
        xr[4*j+0] = v.x; xr[4*j+1] = v.y; xr[4*j+2] = v.z; xr[4*j+3] = v.w;
    }

    __shared__ float smA[NW][K];   // forward warp aggregates
    __shared__ float smB[NW][K];   // backward warp aggregates
    __shared__ float smInit[K];    // backward init = y_fwd[T-1]
    __shared__ float smX0;         // forward init = x[0]

    // ==================== FORWARD pass ====================
    // pass1: zero-init scaled chains y~ = x + q*y~  (FFMA-imm, 4-way ILP)
    float S0 = 0.f, S1 = 0.f, S2 = 0.f, S3 = 0.f;
#pragma unroll
    for (int i = 0; i < CH; ++i) {
        S0 = fmaf(q0, S0, xr[i]);
        S1 = fmaf(q1, S1, xr[i]);
        S2 = fmaf(q2, S2, xr[i]);
        S3 = fmaf(q3, S3, xr[i]);
    }
    S0 *= s0; S1 *= s1; S2 *= s2; S3 *= s3;      // true-units chunk ends

    // warp inclusive scan (per-k depth: k0,k1 full; k2 4 steps; k3 3 steps)
    {
        float v;
        v = __shfl_up_sync(ALL, S0, 1);  if (lane >= 1)  S0 = fmaf(P8_0,  v, S0);
        v = __shfl_up_sync(ALL, S0, 2);  if (lane >= 2)  S0 = fmaf(P16_0, v, S0);
        v = __shfl_up_sync(ALL, S0, 4);  if (lane >= 4)  S0 = fmaf(P32_0, v, S0);
        v = __shfl_up_sync(ALL, S0, 8);  if (lane >= 8)  S0 = fmaf(P64_0, v, S0);
        v = __shfl_up_sync(ALL, S0, 16); if (lane >= 16) S0 = fmaf(P128_0, v, S0);
        v = __shfl_up_sync(ALL, S1, 1);  if (lane >= 1)  S1 = fmaf(P8_1,  v, S1);
        v = __shfl_up_sync(ALL, S1, 2);  if (lane >= 2)  S1 = fmaf(P16_1, v, S1);
        v = __shfl_up_sync(ALL, S1, 4);  if (lane >= 4)  S1 = fmaf(P32_1, v, S1);
        v = __shfl_up_sync(ALL, S1, 8);  if (lane >= 8)  S1 = fmaf(P64_1, v, S1);
        v = __shfl_up_sync(ALL, S1, 16); if (lane >= 16) S1 = fmaf(P128_1, v, S1);
        v = __shfl_up_sync(ALL, S2, 1);  if (lane >= 1)  S2 = fmaf(P8_2,  v, S2);
        v = __shfl_up_sync(ALL, S2, 2);  if (lane >= 2)  S2 = fmaf(P16_2, v, S2);
        v = __shfl_up_sync(ALL, S2, 4);  if (lane >= 4)  S2 = fmaf(P32_2, v, S2);
        v = __shfl_up_sync(ALL, S2, 8);  if (lane >= 8)  S2 = fmaf(P64_2, v, S2);
        v = __shfl_up_sync(ALL, S3, 1);  if (lane >= 1)  S3 = fmaf(P8_3,  v, S3);
        v = __shfl_up_sync(ALL, S3, 2);  if (lane >= 2)  S3 = fmaf(P16_3, v, S3);
        v = __shfl_up_sync(ALL, S3, 4);  if (lane >= 4)  S3 = fmaf(P32_3, v, S3);
    }

    if (lane == 31) { smA[w][0] = S0; smA[w][1] = S1; smA[w][2] = S2; smA[w][3] = S3; }
    if (tid == 0)   smX0 = xr[0];
    __syncthreads();

    // carry into this chunk: carry = Q8^lane * H_w + S_{lane-1}
    float carry[K];
    {
        float v0 = __shfl_up_sync(ALL, S0, 1);
        float v1 = __shfl_up_sync(ALL, S1, 1);
        float v2 = __shfl_up_sync(ALL, S2, 1);
        float v3 = __shfl_up_sync(ALL, S3, 1);
        float sx0 = (lane > 0) ? v0 : 0.f, sx1 = (lane > 0) ? v1 : 0.f;
        float sx2 = (lane > 0) ? v2 : 0.f, sx3 = (lane > 0) ? v3 : 0.f;
        const float x0s = smX0;
        float H0 = x0s, H1 = x0s, H2 = x0s, H3 = x0s;
#pragma unroll
        for (int j = 0; j < NW - 1; ++j) {
            if (j < w) {
                H0 = fmaf(P256_0, H0, smA[j][0]);
                H1 = fmaf(P256_1, H1, smA[j][1]);
                H2 = fmaf(P256_2, H2, smA[j][2]);
                H3 = fmaf(P256_3, H3, smA[j][3]);
            }
        }
        carry[0] = fmaf(Qlf[0], H0, sx0);
        carry[1] = fmaf(Qlf[1], H1, sx1);
        carry[2] = fmaf(Qlf[2], H2, sx2);
        carry[3] = fmaf(Qlf[3], H3, sx3);
    }

    // pass2: exact chain, keep scaled forward signal y~ = y/s
    float yf0[CH], yf1[CH], yf2[CH], yf3[CH];
    {
        float y0 = carry[0] * (1.f / s0), y1 = carry[1] * (1.f / s1);
        float y2 = carry[2] * (1.f / s2), y3 = carry[3] * (1.f / s3);
#pragma unroll
        for (int i = 0; i < CH; ++i) {
            y0 = fmaf(q0, y0, xr[i]); yf0[i] = y0;
            y1 = fmaf(q1, y1, xr[i]); yf1[i] = y1;
            y2 = fmaf(q2, y2, xr[i]); yf2[i] = y2;
            y3 = fmaf(q3, y3, xr[i]); yf3[i] = y3;
        }
    }

    // ==================== BACKWARD pass ====================
    // z# = z/s^2 satisfies z# = y~ + q*z#
    float B0 = 0.f, B1 = 0.f, B2 = 0.f, B3 = 0.f;
#pragma unroll
    for (int i = CH - 1; i >= 0; --i) {
        B0 = fmaf(q0, B0, yf0[i]);
        B1 = fmaf(q1, B1, yf1[i]);
        B2 = fmaf(q2, B2, yf2[i]);
        B3 = fmaf(q3, B3, yf3[i]);
    }
    B0 *= s0 * s0; B1 *= s1 * s1; B2 *= s2 * s2; B3 *= s3 * s3;

    // descending warp scan
    {
        float v;
        v = __shfl_down_sync(ALL, B0, 1);  if (lane < 31) B0 = fmaf(P8_0,  v, B0);
        v = __shfl_down_sync(ALL, B0, 2);  if (lane < 30) B0 = fmaf(P16_0, v, B0);
        v = __shfl_down_sync(ALL, B0, 4);  if (lane < 28) B0 = fmaf(P32_0, v, B0);
        v = __shfl_down_sync(ALL, B0, 8);  if (lane < 24) B0 = fmaf(P64_0, v, B0);
        v = __shfl_down_sync(ALL, B0, 16); if (lane < 16) B0 = fmaf(P128_0, v, B0);
        v = __shfl_down_sync(ALL, B1, 1);  if (lane < 31) B1 = fmaf(P8_1,  v, B1);
        v = __shfl_down_sync(ALL, B1, 2);  if (lane < 30) B1 = fmaf(P16_1, v, B1);
        v = __shfl_down_sync(ALL, B1, 4);  if (lane < 28) B1 = fmaf(P32_1, v, B1);
        v = __shfl_down_sync(ALL, B1, 8);  if (lane < 24) B1 = fmaf(P64_1, v, B1);
        v = __shfl_down_sync(ALL, B1, 16); if (lane < 16) B1 = fmaf(P128_1, v, B1);
        v = __shfl_down_sync(ALL, B2, 1);  if (lane < 31) B2 = fmaf(P8_2,  v, B2);
        v = __shfl_down_sync(ALL, B2, 2);  if (lane < 30) B2 = fmaf(P16_2, v, B2);
        v = __shfl_down_sync(ALL, B2, 4);  if (lane < 28) B2 = fmaf(P32_2, v, B2);
        v = __shfl_down_sync(ALL, B2, 8);  if (lane < 24) B2 = fmaf(P64_2, v, B2);
        v = __shfl_down_sync(ALL, B3, 1);  if (lane < 31) B3 = fmaf(P8_3,  v, B3);
        v = __shfl_down_sync(ALL, B3, 2);  if (lane < 30) B3 = fmaf(P16_3, v, B3);
        v = __shfl_down_sync(ALL, B3, 4);  if (lane < 28) B3 = fmaf(P32_3, v, B3);
    }

    if (lane == 0) { smB[w][0] = B0; smB[w][1] = B1; smB[w][2] = B2; smB[w][3] = B3; }
    if (tid == T / CH - 1) {
        smInit[0] = s0 * yf0[CH - 1];   // y_fwd[T-1] in true units
        smInit[1] = s1 * yf1[CH - 1];
        smInit[2] = s2 * yf2[CH - 1];
        smInit[3] = s3 * yf3[CH - 1];
    }
    __syncthreads();

    float carB[K];
    {
        float v0 = __shfl_down_sync(ALL, B0, 1);
        float v1 = __shfl_down_sync(ALL, B1, 1);
        float v2 = __shfl_down_sync(ALL, B2, 1);
        float v3 = __shfl_down_sync(ALL, B3, 1);
        float sx0 = (lane < 31) ? v0 : 0.f, sx1 = (lane < 31) ? v1 : 0.f;
        float sx2 = (lane < 31) ? v2 : 0.f, sx3 = (lane < 31) ? v3 : 0.f;
        float H0 = smInit[0], H1 = smInit[1], H2 = smInit[2], H3 = smInit[3];
#pragma unroll
        for (int j = NW - 1; j >= 1; --j) {
            if (j > w) {
                H0 = fmaf(P256_0, H0, smB[j][0]);
                H1 = fmaf(P256_1, H1, smB[j][1]);
                H2 = fmaf(P256_2, H2, smB[j][2]);
                H3 = fmaf(P256_3, H3, smB[j][3]);
            }
        }
        carB[0] = fmaf(Qlb[0], H0, sx0);
        carB[1] = fmaf(Qlb[1], H1, sx1);
        carB[2] = fmaf(Qlb[2], H2, sx2);
        carB[3] = fmaf(Qlb[3], H3, sx3);
    }

    // pass2 backward + fused mix + PCEN epilogue + float4 stores
    {
        float z0 = carB[0] * (1.f / (s0 * s0)), z1 = carB[1] * (1.f / (s1 * s1));
        float z2 = carB[2] * (1.f / (s2 * s2)), z3 = carB[3] * (1.f / (s3 * s3));
        float ob[CH];
#pragma unroll
        for (int i = CH - 1; i >= 0; --i) {
            z0 = fmaf(q0, z0, yf0[i]);
            z1 = fmaf(q1, z1, yf1[i]);
            z2 = fmaf(q2, z2, yf2[i]);
            z3 = fmaf(q3, z3, yf3[i]);
            float M = 1e-6f;                                // M + eps accumulator
            M = fmaf(ws[0], z0, M);
            M = fmaf(ws[1], z1, M);
            M = fmaf(ws[2], z2, M);
            M = fmaf(ws[3], z3, M);
            float Mp = ex2_(fmaf(nalpha, lg2_(M), c2));     // (M+eps)^(-a)/delta
            float u  = fmaf(xr[i], Mp, 1.0f);
            ob[i] = fmaf(dr, ex2_(rr * lg2_(u)), -dr);
        }
        float4* ov = reinterpret_cast<float4*>(out + base + tid * CH);
#pragma unroll
        for (int j = 0; j < CH / 4; ++j)
            ov[j] = make_float4(ob[4*j+0], ob[4*j+1], ob[4*j+2], ob[4*j+3]);
    }
}

extern "C" void kernel_launch(void* const* d_in, const int* in_sizes, int n_in,
                              void* d_out, int out_size)
{
    const float* x   = (const float*)d_in[0];
    const float* isa = (const float*)d_in[1];
    const float* ldl = (const float*)d_in[2];
    const float* isr = (const float*)d_in[3];
    const float* zks = (const float*)d_in[4];
    float* out = (float*)d_out;

    const int P    = in_sizes[1];                 // 4
    const int F    = in_sizes[4] / (P * 4);       // 128 (z_ks is [P,K,F], K=4)
    const int rows = in_sizes[0] / 2048;          // B*P*F = 8192

    pcen_kernel<<<rows, 256>>>(x, isa, ldl, isr, zks, out, P, F);
}

// round 8
// speedup vs baseline: 1.3709x; 1.3709x over previous
#include <cuda_runtime.h>

// PCEN stack, round 7: partial-fraction filtfilt (exact, incl. boundaries).
//
// Identity (derived + hand-verified on T=1,2 against the reference recurrences):
//   forward:  A[t] = x[t] + q*A[t-1],  A[-1] = x[0]/s      (scaled fwd filter)
//   backward: G[t] = x[t] + q*G[t+1],  G[T]  = A[T-1]      (virtual init)
//   filtfilt: z[t] = s/(2-s) * (A[t] + G[t] - x[t])
// The backward scan runs on x (not on the stored forward output), so the
// 64-reg yf[4][16] array from R2 is gone; only Mpart[16] (the weighted
// forward mix) is kept. Regs ~123 -> ~75 => 6 blocks/SM at 128 thr, CH=16.
//
// Epilogue identities (validated ~1.2e-6 in R5/R6):
//   log(EPS)+log1p(M/EPS) = log(M+EPS)
//   M'/delta = exp2(-alpha*lg2(M+EPS) - ld*log2e)
//   (x*M+d)^r - d^r = d^r*(exp2(r*lg2(1 + x*M'/d)) - 1)

static __device__ __forceinline__ float ex2_(float v) {
    float r; asm("ex2.approx.f32 %0, %1;" : "=f"(r) : "f"(v)); return r;
}
static __device__ __forceinline__ float lg2_(float v) {
    float r; asm("lg2.approx.f32 %0, %1;" : "=f"(r) : "f"(v)); return r;
}

static constexpr __host__ __device__ double dpow(double b, int n) {
    double r = 1.0;
    for (int i = 0; i < n; ++i) r *= b;
    return r;
}
static constexpr __host__ __device__ float cpf(double v) {
    return (v < 1.0e-37 && v > -1.0e-37) ? 0.0f : (float)v;
}

static constexpr float s0 = 0.015f, s1 = 0.04f, s2 = 0.1f, s3 = 0.25f;
static constexpr float q0 = 1.f - s0, q1 = 1.f - s1, q2 = 1.f - s2, q3 = 1.f - s3;
// warp-scan step factors Q16^(2^j), Q16 = q^16 (CH=16)
static constexpr float P16_0  = cpf(dpow(q0, 16)),  P16_1  = cpf(dpow(q1, 16)),
                       P16_2  = cpf(dpow(q2, 16)),  P16_3  = cpf(dpow(q3, 16));
static constexpr float P32_0  = cpf(dpow(q0, 32)),  P32_1  = cpf(dpow(q1, 32)),
                       P32_2  = cpf(dpow(q2, 32)),  P32_3  = cpf(dpow(q3, 32));
static constexpr float P64_0  = cpf(dpow(q0, 64)),  P64_1  = cpf(dpow(q1, 64)),
                       P64_2  = cpf(dpow(q2, 64)),  P64_3  = cpf(dpow(q3, 64));
static constexpr float P128_0 = cpf(dpow(q0, 128)), P128_1 = cpf(dpow(q1, 128)),
                       P128_2 = cpf(dpow(q2, 128));
static constexpr float P256_0 = cpf(dpow(q0, 256)), P256_1 = cpf(dpow(q1, 256));
// cross-warp fold factor q^512 (warp = 32 lanes * 16 elems)
static constexpr float P512_0 = cpf(dpow(q0, 512)), P512_1 = cpf(dpow(q1, 512)),
                       P512_2 = cpf(dpow(q2, 512)), P512_3 = cpf(dpow(q3, 512));

__global__ __launch_bounds__(128, 6)
void pcen_kernel(const float* __restrict__ x,
                 const float* __restrict__ i_sig_alpha,
                 const float* __restrict__ log_delta,
                 const float* __restrict__ i_sig_r,
                 const float* __restrict__ z_ks,
                 float* __restrict__ out,
                 int P, int F)
{
    constexpr int T = 2048, CH = 16, K = 4, NW = 4;
    constexpr unsigned ALL = 0xffffffffu;

    const int row  = blockIdx.x;                 // ((b*P)+p)*F + f
    const int p    = (row / F) % P;
    const int f    = row % F;
    const int base = row * T;
    const int tid  = threadIdx.x;
    const int lane = tid & 31;
    const int w    = tid >> 5;

    // per-lane geometric factors Q16^lane (fwd) / Q16^(31-lane) (bwd)
    const float lf = (float)lane, lb = (float)(31 - lane);
    const float g0 = lg2_(P16_0), g1 = lg2_(P16_1), g2 = lg2_(P16_2), g3 = lg2_(P16_3);
    const float Qlf0 = ex2_(lf * g0), Qlf1 = ex2_(lf * g1),
                Qlf2 = ex2_(lf * g2), Qlf3 = ex2_(lf * g3);
    const float Qlb0 = ex2_(lb * g0), Qlb1 = ex2_(lb * g1),
                Qlb2 = ex2_(lb * g2), Qlb3 = ex2_(lb * g3);

    // ---- per-(p,f) scalars ----
    const float alpha  = 1.0f / (1.0f + __expf(-i_sig_alpha[p]));
    const float rr     = 1.0f / (1.0f + __expf(-i_sig_r[p]));
    const float ld     = log_delta[p];
    const float nalpha = -alpha;
    const float c2     = -ld * 1.4426950408889634f;            // -ld*log2e
    const float dr     = ex2_(rr * ld * 1.4426950408889634f);  // delta^r

    float zk0 = z_ks[(p * K + 0) * F + f];
    float zk1 = z_ks[(p * K + 1) * F + f];
    float zk2 = z_ks[(p * K + 2) * F + f];
    float zk3 = z_ks[(p * K + 3) * F + f];
    float zm = fmaxf(fmaxf(zk0, zk1), fmaxf(zk2, zk3));
    float e0 = __expf(zk0 - zm), e1 = __expf(zk1 - zm),
          e2 = __expf(zk2 - zm), e3 = __expf(zk3 - zm);
    const float inv_sum = 1.0f / (e0 + e1 + e2 + e3);
    // wc_k = softmax_k * s_k/(2-s_k)   (z_k = s/(2-s) * (A+G-x))
    const float wc0 = e0 * inv_sum * (s0 / (2.f - s0));
    const float wc1 = e1 * inv_sum * (s1 / (2.f - s1));
    const float wc2 = e2 * inv_sum * (s2 / (2.f - s2));
    const float wc3 = e3 * inv_sum * (s3 / (2.f - s3));
    const float nwcx = -(wc0 + wc1 + wc2 + wc3);   // coefficient of -x[t]

    // ---- load x: 16 contiguous floats (4x LDG.128) ----
    float xr[CH];
    const float4* xv = reinterpret_cast<const float4*>(x + base + tid * CH);
#pragma unroll
    for (int j = 0; j < CH / 4; ++j) {
        float4 v = xv[j];
        xr[4*j+0] = v.x; xr[4*j+1] = v.y; xr[4*j+2] = v.z; xr[4*j+3] = v.w;
    }

    __shared__ float smA[NW][K];   // forward warp aggregates
    __shared__ float smB[NW][K];   // backward warp aggregates
    __shared__ float smInit[K];    // backward virtual init = A[T-1]
    __shared__ float smX0;         // x[0]

    // ===== fused pass1: fwd + bwd zero-init chunk sums on x (8-way ILP) =====
    float E0 = 0.f, E1 = 0.f, E2 = 0.f, E3 = 0.f;   // fwd: ends at chunk last elem
    float B0 = 0.f, B1 = 0.f, B2 = 0.f, B3 = 0.f;   // bwd: ends at chunk first elem
#pragma unroll
    for (int i = 0; i < CH; ++i) {
        float xa = xr[i], xb = xr[CH - 1 - i];
        E0 = fmaf(q0, E0, xa);
        E1 = fmaf(q1, E1, xa);
        E2 = fmaf(q2, E2, xa);
        E3 = fmaf(q3, E3, xa);
        B0 = fmaf(q0, B0, xb);
        B1 = fmaf(q1, B1, xb);
        B2 = fmaf(q2, B2, xb);
        B3 = fmaf(q3, B3, xb);
    }

    // ===== warp scans (fwd ascending on E, bwd descending on B) =====
    // per-k truncation: k0,k1 full 5 steps; k2 4 steps (q^256~2e-12);
    // k3 3 steps (q^128~1e-16).
    {
        float v;
        v = __shfl_up_sync(ALL, E0, 1);  if (lane >= 1)  E0 = fmaf(P16_0, v, E0);
        v = __shfl_up_sync(ALL, E0, 2);  if (lane >= 2)  E0 = fmaf(P32_0, v, E0);
        v = __shfl_up_sync(ALL, E0, 4);  if (lane >= 4)  E0 = fmaf(P64_0, v, E0);
        v = __shfl_up_sync(ALL, E0, 8);  if (lane >= 8)  E0 = fmaf(P128_0, v, E0);
        v = __shfl_up_sync(ALL, E0, 16); if (lane >= 16) E0 = fmaf(P256_0, v, E0);
        v = __shfl_up_sync(ALL, E1, 1);  if (lane >= 1)  E1 = fmaf(P16_1, v, E1);
        v = __shfl_up_sync(ALL, E1, 2);  if (lane >= 2)  E1 = fmaf(P32_1, v, E1);
        v = __shfl_up_sync(ALL, E1, 4);  if (lane >= 4)  E1 = fmaf(P64_1, v, E1);
        v = __shfl_up_sync(ALL, E1, 8);  if (lane >= 8)  E1 = fmaf(P128_1, v, E1);
        v = __shfl_up_sync(ALL, E1, 16); if (lane >= 16) E1 = fmaf(P256_1, v, E1);
        v = __shfl_up_sync(ALL, E2, 1);  if (lane >= 1)  E2 = fmaf(P16_2, v, E2);
        v = __shfl_up_sync(ALL, E2, 2);  if (lane >= 2)  E2 = fmaf(P32_2, v, E2);
        v = __shfl_up_sync(ALL, E2, 4);  if (lane >= 4)  E2 = fmaf(P64_2, v, E2);
        v = __shfl_up_sync(ALL, E2, 8);  if (lane >= 8)  E2 = fmaf(P128_2, v, E2);
        v = __shfl_up_sync(ALL, E3, 1);  if (lane >= 1)  E3 = fmaf(P16_3, v, E3);
        v = __shfl_up_sync(ALL, E3, 2);  if (lane >= 2)  E3 = fmaf(P32_3, v, E3);
        v = __shfl_up_sync(ALL, E3, 4);  if (lane >= 4)  E3 = fmaf(P64_3, v, E3);

        v = __shfl_down_sync(ALL, B0, 1);  if (lane < 31) B0 = fmaf(P16_0, v, B0);
        v = __shfl_down_sync(ALL, B0, 2);  if (lane < 30) B0 = fmaf(P32_0, v, B0);
        v = __shfl_down_sync(ALL, B0, 4);  if (lane < 28) B0 = fmaf(P64_0, v, B0);
        v = __shfl_down_sync(ALL, B0, 8);  if (lane < 24) B0 = fmaf(P128_0, v, B0);
        v = __shfl_down_sync(ALL, B0, 16); if (lane < 16) B0 = fmaf(P256_0, v, B0);
        v = __shfl_down_sync(ALL, B1, 1);  if (lane < 31) B1 = fmaf(P16_1, v, B1);
        v = __shfl_down_sync(ALL, B1, 2);  if (lane < 30) B1 = fmaf(P32_1, v, B1);
        v = __shfl_down_sync(ALL, B1, 4);  if (lane < 28) B1 = fmaf(P64_1, v, B1);
        v = __shfl_down_sync(ALL, B1, 8);  if (lane < 24) B1 = fmaf(P128_1, v, B1);
        v = __shfl_down_sync(ALL, B1, 16); if (lane < 16) B1 = fmaf(P256_1, v, B1);
        v = __shfl_down_sync(ALL, B2, 1);  if (lane < 31) B2 = fmaf(P16_2, v, B2);
        v = __shfl_down_sync(ALL, B2, 2);  if (lane < 30) B2 = fmaf(P32_2, v, B2);
        v = __shfl_down_sync(ALL, B2, 4);  if (lane < 28) B2 = fmaf(P64_2, v, B2);
        v = __shfl_down_sync(ALL, B2, 8);  if (lane < 24) B2 = fmaf(P128_2, v, B2);
        v = __shfl_down_sync(ALL, B3, 1);  if (lane < 31) B3 = fmaf(P16_3, v, B3);
        v = __shfl_down_sync(ALL, B3, 2);  if (lane < 30) B3 = fmaf(P32_3, v, B3);
        v = __shfl_down_sync(ALL, B3, 4);  if (lane < 28) B3 = fmaf(P64_3, v, B3);
    }

    if (lane == 31) { smA[w][0] = E0; smA[w][1] = E1; smA[w][2] = E2; smA[w][3] = E3; }
    if (lane == 0)  { smB[w][0] = B0; smB[w][1] = B1; smB[w][2] = B2; smB[w][3] = B3; }
    if (tid == 0)   smX0 = xr[0];
    __syncthreads();

    // ===== forward carries: car = Q16^lane * H_w + Escan[lane-1] =====
    float car0, car1, car2, car3;
    {
        float v0 = __shfl_up_sync(ALL, E0, 1);
        float v1 = __shfl_up_sync(ALL, E1, 1);
        float v2 = __shfl_up_sync(ALL, E2, 1);
        float v3 = __shfl_up_sync(ALL, E3, 1);
        float sx0 = (lane > 0) ? v0 : 0.f, sx1 = (lane > 0) ? v1 : 0.f;
        float sx2 = (lane > 0) ? v2 : 0.f, sx3 = (lane > 0) ? v3 : 0.f;
        const float x0s = smX0;
        float H0 = x0s * (1.f / s0), H1 = x0s * (1.f / s1);   // seed A[-1] = x0/s
        float H2 = x0s * (1.f / s2), H3 = x0s * (1.f / s3);
#pragma unroll
        for (int j = 0; j < NW - 1; ++j) {
            if (j < w) {
                H0 = fmaf(P512_0, H0, smA[j][0]);
                H1 = fmaf(P512_1, H1, smA[j][1]);
                H2 = fmaf(P512_2, H2, smA[j][2]);
                H3 = fmaf(P512_3, H3, smA[j][3]);
            }
        }
        car0 = fmaf(Qlf0, H0, sx0);
        car1 = fmaf(Qlf1, H1, sx1);
        car2 = fmaf(Qlf2, H2, sx2);
        car3 = fmaf(Qlf3, H3, sx3);
    }

    // ===== fwd pass2: A chains + weighted partial mix (keeps only Mpart[16]) =====
    float Mpart[CH];
    {
        float a0 = car0, a1 = car1, a2 = car2, a3 = car3;
#pragma unroll
        for (int i = 0; i < CH; ++i) {
            a0 = fmaf(q0, a0, xr[i]);
            a1 = fmaf(q1, a1, xr[i]);
            a2 = fmaf(q2, a2, xr[i]);
            a3 = fmaf(q3, a3, xr[i]);
            float m = fmaf(wc0, a0, 1e-6f);   // eps folded in
            m = fmaf(wc1, a1, m);
            m = fmaf(wc2, a2, m);
            Mpart[i] = fmaf(wc3, a3, m);
        }
        if (tid == T / CH - 1) {              // A[T-1] -> backward virtual init
            smInit[0] = a0; smInit[1] = a1; smInit[2] = a2; smInit[3] = a3;
        }
    }
    __syncthreads();

    // ===== backward carries: cb = Q16^(31-lane) * Hb_w + Bscan[lane+1] =====
    float cb0, cb1, cb2, cb3;
    {
        float v0 = __shfl_down_sync(ALL, B0, 1);
        float v1 = __shfl_down_sync(ALL, B1, 1);
        float v2 = __shfl_down_sync(ALL, B2, 1);
        float v3 = __shfl_down_sync(ALL, B3, 1);
        float sx0 = (lane < 31) ? v0 : 0.f, sx1 = (lane < 31) ? v1 : 0.f;
        float sx2 = (lane < 31) ? v2 : 0.f, sx3 = (lane < 31) ? v3 : 0.f;
        float H0 = smInit[0], H1 = smInit[1], H2 = smInit[2], H3 = smInit[3];
#pragma unroll
        for (int j = NW - 1; j >= 1; --j) {
            if (j > w) {
                H0 = fmaf(P512_0, H0, smB[j][0]);
                H1 = fmaf(P512_1, H1, smB[j][1]);
                H2 = fmaf(P512_2, H2, smB[j][2]);
                H3 = fmaf(P512_3, H3, smB[j][3]);
            }
        }
        cb0 = fmaf(Qlb0, H0, sx0);
        cb1 = fmaf(Qlb1, H1, sx1);
        cb2 = fmaf(Qlb2, H2, sx2);
        cb3 = fmaf(Qlb3, H3, sx3);
    }

    // ===== bwd pass2 (G chains on x) + final mix + PCEN epilogue + stores =====
    {
        float gg0 = cb0, gg1 = cb1, gg2 = cb2, gg3 = cb3;
        float* outp = out + base + tid * CH;
#pragma unroll
        for (int jg = CH / 4 - 1; jg >= 0; --jg) {
            float o0, o1, o2, o3;
#pragma unroll
            for (int ii = 3; ii >= 0; --ii) {
                const int i = 4 * jg + ii;
                gg0 = fmaf(q0, gg0, xr[i]);
                gg1 = fmaf(q1, gg1, xr[i]);
                gg2 = fmaf(q2, gg2, xr[i]);
                gg3 = fmaf(q3, gg3, xr[i]);
                float M = fmaf(nwcx, xr[i], Mpart[i]);   // Mpart + Σ wc*G - Σwc*x
                M = fmaf(wc0, gg0, M);
                M = fmaf(wc1, gg1, M);
                M = fmaf(wc2, gg2, M);
                M = fmaf(wc3, gg3, M);
                float Mp = ex2_(fmaf(nalpha, lg2_(M), c2));   // (M+eps)^(-a)/delta
                float u  = fmaf(xr[i], Mp, 1.0f);
                float o  = fmaf(dr, ex2_(rr * lg2_(u)), -dr);
                if (ii == 0) o0 = o; else if (ii == 1) o1 = o;
                else if (ii == 2) o2 = o; else o3 = o;
            }
            reinterpret_cast<float4*>(outp)[jg] = make_float4(o0, o1, o2, o3);
        }
    }
}

extern "C" void kernel_launch(void* const* d_in, const int* in_sizes, int n_in,
                              void* d_out, int out_size)
{
    const float* x   = (const float*)d_in[0];
    const float* isa = (const float*)d_in[1];
    const float* ldl = (const float*)d_in[2];
    const float* isr = (const float*)d_in[3];
    const float* zks = (const float*)d_in[4];
    float* out = (float*)d_out;

    const int P    = in_sizes[1];                 // 4
    const int F    = in_sizes[4] / (P * 4);       // 128 (z_ks is [P,K,F], K=4)
    const int rows = in_sizes[0] / 2048;          // B*P*F = 8192

    pcen_kernel<<<rows, 128>>>(x, isa, ldl, isr, zks, out, P, F);
}

// round 9
// speedup vs baseline: 1.5423x; 1.1250x over previous
#include <cuda_runtime.h>

// PCEN stack, round 8: R7 partial-fraction design + Mpart moved to shared
// memory to cut registers 79 -> ~63 and raise occupancy 6 -> 8 blocks/SM.
//
// Identity (exact, incl. scipy boundary conditions):
//   forward:  A[t] = x[t] + q*A[t-1],  A[-1] = x[0]/s
//   backward: G[t] = x[t] + q*G[t+1],  G[T]  = A[T-1]
//   filtfilt: z[t] = s/(2-s) * (A[t] + G[t] - x[t])
//
// Epilogue identities (validated ~1.1e-6):
//   log(EPS)+log1p(M/EPS) = log(M+EPS)
//   M'/delta = exp2(-alpha*lg2(M+EPS) - ld*log2e)
//   (x*M+d)^r - d^r = d^r*(exp2(r*lg2(1 + x*M'/d)) - 1)

static __device__ __forceinline__ float ex2_(float v) {
    float r; asm("ex2.approx.f32 %0, %1;" : "=f"(r) : "f"(v)); return r;
}
static __device__ __forceinline__ float lg2_(float v) {
    float r; asm("lg2.approx.f32 %0, %1;" : "=f"(r) : "f"(v)); return r;
}

static constexpr __host__ __device__ double dpow(double b, int n) {
    double r = 1.0;
    for (int i = 0; i < n; ++i) r *= b;
    return r;
}
static constexpr __host__ __device__ float cpf(double v) {
    return (v < 1.0e-37 && v > -1.0e-37) ? 0.0f : (float)v;
}

static constexpr float s0 = 0.015f, s1 = 0.04f, s2 = 0.1f, s3 = 0.25f;
static constexpr float q0 = 1.f - s0, q1 = 1.f - s1, q2 = 1.f - s2, q3 = 1.f - s3;
static constexpr float P16_0  = cpf(dpow(q0, 16)),  P16_1  = cpf(dpow(q1, 16)),
                       P16_2  = cpf(dpow(q2, 16)),  P16_3  = cpf(dpow(q3, 16));
static constexpr float P32_0  = cpf(dpow(q0, 32)),  P32_1  = cpf(dpow(q1, 32)),
                       P32_2  = cpf(dpow(q2, 32)),  P32_3  = cpf(dpow(q3, 32));
static constexpr float P64_0  = cpf(dpow(q0, 64)),  P64_1  = cpf(dpow(q1, 64)),
                       P64_2  = cpf(dpow(q2, 64)),  P64_3  = cpf(dpow(q3, 64));
static constexpr float P128_0 = cpf(dpow(q0, 128)), P128_1 = cpf(dpow(q1, 128)),
                       P128_2 = cpf(dpow(q2, 128));
static constexpr float P256_0 = cpf(dpow(q0, 256)), P256_1 = cpf(dpow(q1, 256));
static constexpr float P512_0 = cpf(dpow(q0, 512)), P512_1 = cpf(dpow(q1, 512)),
                       P512_2 = cpf(dpow(q2, 512)), P512_3 = cpf(dpow(q3, 512));

__global__ __launch_bounds__(128, 8)
void pcen_kernel(const float* __restrict__ x,
                 const float* __restrict__ i_sig_alpha,
                 const float* __restrict__ log_delta,
                 const float* __restrict__ i_sig_r,
                 const float* __restrict__ z_ks,
                 float* __restrict__ out,
                 int P, int F)
{
    constexpr int T = 2048, CH = 16, K = 4, NW = 4;
    constexpr int MPAD = 17;     // per-thread smem stride (floats), conflict-free
    constexpr unsigned ALL = 0xffffffffu;

    const int row  = blockIdx.x;                 // ((b*P)+p)*F + f
    const int p    = (row / F) % P;
    const int f    = row % F;
    const int base = row * T;
    const int tid  = threadIdx.x;
    const int lane = tid & 31;
    const int w    = tid >> 5;

    // per-lane geometric factors Q16^lane (fwd) / Q16^(31-lane) (bwd)
    const float lf = (float)lane, lb = (float)(31 - lane);
    const float g0 = lg2_(P16_0), g1 = lg2_(P16_1), g2 = lg2_(P16_2), g3 = lg2_(P16_3);
    const float Qlf0 = ex2_(lf * g0), Qlf1 = ex2_(lf * g1),
                Qlf2 = ex2_(lf * g2), Qlf3 = ex2_(lf * g3);
    const float Qlb0 = ex2_(lb * g0), Qlb1 = ex2_(lb * g1),
                Qlb2 = ex2_(lb * g2), Qlb3 = ex2_(lb * g3);

    // ---- per-(p,f) scalars ----
    const float alpha  = 1.0f / (1.0f + __expf(-i_sig_alpha[p]));
    const float rr     = 1.0f / (1.0f + __expf(-i_sig_r[p]));
    const float ld     = log_delta[p];
    const float nalpha = -alpha;
    const float c2     = -ld * 1.4426950408889634f;            // -ld*log2e
    const float dr     = ex2_(rr * ld * 1.4426950408889634f);  // delta^r

    float zk0 = z_ks[(p * K + 0) * F + f];
    float zk1 = z_ks[(p * K + 1) * F + f];
    float zk2 = z_ks[(p * K + 2) * F + f];
    float zk3 = z_ks[(p * K + 3) * F + f];
    float zm = fmaxf(fmaxf(zk0, zk1), fmaxf(zk2, zk3));
    float e0 = __expf(zk0 - zm), e1 = __expf(zk1 - zm),
          e2 = __expf(zk2 - zm), e3 = __expf(zk3 - zm);
    const float inv_sum = 1.0f / (e0 + e1 + e2 + e3);
    // wc_k = softmax_k * s_k/(2-s_k)   (z_k = s/(2-s) * (A+G-x))
    const float wc0 = e0 * inv_sum * (s0 / (2.f - s0));
    const float wc1 = e1 * inv_sum * (s1 / (2.f - s1));
    const float wc2 = e2 * inv_sum * (s2 / (2.f - s2));
    const float wc3 = e3 * inv_sum * (s3 / (2.f - s3));
    const float nwcx = -(wc0 + wc1 + wc2 + wc3);   // coefficient of -x[t]

    // ---- load x: 16 contiguous floats (4x LDG.128) ----
    float xr[CH];
    const float4* xv = reinterpret_cast<const float4*>(x + base + tid * CH);
#pragma unroll
    for (int j = 0; j < CH / 4; ++j) {
        float4 v = xv[j];
        xr[4*j+0] = v.x; xr[4*j+1] = v.y; xr[4*j+2] = v.z; xr[4*j+3] = v.w;
    }

    __shared__ float smA[NW][K];   // forward warp aggregates
    __shared__ float smB[NW][K];   // backward warp aggregates
    __shared__ float smInit[K];    // backward virtual init = A[T-1]
    __shared__ float smX0;         // x[0]
    __shared__ float smM[128 * MPAD];  // per-thread Mpart slab (private, no sync)

    // ===== fused pass1: fwd + bwd zero-init chunk sums on x (8-way ILP) =====
    float E0 = 0.f, E1 = 0.f, E2 = 0.f, E3 = 0.f;   // fwd: ends at chunk last elem
    float B0 = 0.f, B1 = 0.f, B2 = 0.f, B3 = 0.f;   // bwd: ends at chunk first elem
#pragma unroll
    for (int i = 0; i < CH; ++i) {
        float xa = xr[i], xb = xr[CH - 1 - i];
        E0 = fmaf(q0, E0, xa);
        E1 = fmaf(q1, E1, xa);
        E2 = fmaf(q2, E2, xa);
        E3 = fmaf(q3, E3, xa);
        B0 = fmaf(q0, B0, xb);
        B1 = fmaf(q1, B1, xb);
        B2 = fmaf(q2, B2, xb);
        B3 = fmaf(q3, B3, xb);
    }

    // ===== warp scans (fwd ascending on E, bwd descending on B) =====
    // per-k truncation: k0,k1 full 5 steps; k2 4 steps; k3 3 steps.
    {
        float v;
        v = __shfl_up_sync(ALL, E0, 1);  if (lane >= 1)  E0 = fmaf(P16_0, v, E0);
        v = __shfl_up_sync(ALL, E0, 2);  if (lane >= 2)  E0 = fmaf(P32_0, v, E0);
        v = __shfl_up_sync(ALL, E0, 4);  if (lane >= 4)  E0 = fmaf(P64_0, v, E0);
        v = __shfl_up_sync(ALL, E0, 8);  if (lane >= 8)  E0 = fmaf(P128_0, v, E0);
        v = __shfl_up_sync(ALL, E0, 16); if (lane >= 16) E0 = fmaf(P256_0, v, E0);
        v = __shfl_up_sync(ALL, E1, 1);  if (lane >= 1)  E1 = fmaf(P16_1, v, E1);
        v = __shfl_up_sync(ALL, E1, 2);  if (lane >= 2)  E1 = fmaf(P32_1, v, E1);
        v = __shfl_up_sync(ALL, E1, 4);  if (lane >= 4)  E1 = fmaf(P64_1, v, E1);
        v = __shfl_up_sync(ALL, E1, 8);  if (lane >= 8)  E1 = fmaf(P128_1, v, E1);
        v = __shfl_up_sync(ALL, E1, 16); if (lane >= 16) E1 = fmaf(P256_1, v, E1);
        v = __shfl_up_sync(ALL, E2, 1);  if (lane >= 1)  E2 = fmaf(P16_2, v, E2);
        v = __shfl_up_sync(ALL, E2, 2);  if (lane >= 2)  E2 = fmaf(P32_2, v, E2);
        v = __shfl_up_sync(ALL, E2, 4);  if (lane >= 4)  E2 = fmaf(P64_2, v, E2);
        v = __shfl_up_sync(ALL, E2, 8);  if (lane >= 8)  E2 = fmaf(P128_2, v, E2);
        v = __shfl_up_sync(ALL, E3, 1);  if (lane >= 1)  E3 = fmaf(P16_3, v, E3);
        v = __shfl_up_sync(ALL, E3, 2);  if (lane >= 2)  E3 = fmaf(P32_3, v, E3);
        v = __shfl_up_sync(ALL, E3, 4);  if (lane >= 4)  E3 = fmaf(P64_3, v, E3);

        v = __shfl_down_sync(ALL, B0, 1);  if (lane < 31) B0 = fmaf(P16_0, v, B0);
        v = __shfl_down_sync(ALL, B0, 2);  if (lane < 30) B0 = fmaf(P32_0, v, B0);
        v = __shfl_down_sync(ALL, B0, 4);  if (lane < 28) B0 = fmaf(P64_0, v, B0);
        v = __shfl_down_sync(ALL, B0, 8);  if (lane < 24) B0 = fmaf(P128_0, v, B0);
        v = __shfl_down_sync(ALL, B0, 16); if (lane < 16) B0 = fmaf(P256_0, v, B0);
        v = __shfl_down_sync(ALL, B1, 1);  if (lane < 31) B1 = fmaf(P16_1, v, B1);
        v = __shfl_down_sync(ALL, B1, 2);  if (lane < 30) B1 = fmaf(P32_1, v, B1);
        v = __shfl_down_sync(ALL, B1, 4);  if (lane < 28) B1 = fmaf(P64_1, v, B1);
        v = __shfl_down_sync(ALL, B1, 8);  if (lane < 24) B1 = fmaf(P128_1, v, B1);
        v = __shfl_down_sync(ALL, B1, 16); if (lane < 16) B1 = fmaf(P256_1, v, B1);
        v = __shfl_down_sync(ALL, B2, 1);  if (lane < 31) B2 = fmaf(P16_2, v, B2);
        v = __shfl_down_sync(ALL, B2, 2);  if (lane < 30) B2 = fmaf(P32_2, v, B2);
        v = __shfl_down_sync(ALL, B2, 4);  if (lane < 28) B2 = fmaf(P64_2, v, B2);
        v = __shfl_down_sync(ALL, B2, 8);  if (lane < 24) B2 = fmaf(P128_2, v, B2);
        v = __shfl_down_sync(ALL, B3, 1);  if (lane < 31) B3 = fmaf(P16_3, v, B3);
        v = __shfl_down_sync(ALL, B3, 2);  if (lane < 30) B3 = fmaf(P32_3, v, B3);
        v = __shfl_down_sync(ALL, B3, 4);  if (lane < 28) B3 = fmaf(P64_3, v, B3);
    }

    if (lane == 31) { smA[w][0] = E0; smA[w][1] = E1; smA[w][2] = E2; smA[w][3] = E3; }
    if (lane == 0)  { smB[w][0] = B0; smB[w][1] = B1; smB[w][2] = B2; smB[w][3] = B3; }
    if (tid == 0)   smX0 = xr[0];
    __syncthreads();

    // ===== forward carries: car = Q16^lane * H_w + Escan[lane-1] =====
    float car0, car1, car2, car3;
    {
        float v0 = __shfl_up_sync(ALL, E0, 1);
        float v1 = __shfl_up_sync(ALL, E1, 1);
        float v2 = __shfl_up_sync(ALL, E2, 1);
        float v3 = __shfl_up_sync(ALL, E3, 1);
        float sx0 = (lane > 0) ? v0 : 0.f, sx1 = (lane > 0) ? v1 : 0.f;
        float sx2 = (lane > 0) ? v2 : 0.f, sx3 = (lane > 0) ? v3 : 0.f;
        const float x0s = smX0;
        float H0 = x0s * (1.f / s0), H1 = x0s * (1.f / s1);   // seed A[-1] = x0/s
        float H2 = x0s * (1.f / s2), H3 = x0s * (1.f / s3);
#pragma unroll
        for (int j = 0; j < NW - 1; ++j) {
            if (j < w) {
                H0 = fmaf(P512_0, H0, smA[j][0]);
                H1 = fmaf(P512_1, H1, smA[j][1]);
                H2 = fmaf(P512_2, H2, smA[j][2]);
                H3 = fmaf(P512_3, H3, smA[j][3]);
            }
        }
        car0 = fmaf(Qlf0, H0, sx0);
        car1 = fmaf(Qlf1, H1, sx1);
        car2 = fmaf(Qlf2, H2, sx2);
        car3 = fmaf(Qlf3, H3, sx3);
    }

    // ===== fwd pass2: A chains + weighted partial mix -> smem slab =====
    {
        float* mrow = smM + tid * MPAD;
        float a0 = car0, a1 = car1, a2 = car2, a3 = car3;
#pragma unroll
        for (int i = 0; i < CH; ++i) {
            a0 = fmaf(q0, a0, xr[i]);
            a1 = fmaf(q1, a1, xr[i]);
            a2 = fmaf(q2, a2, xr[i]);
            a3 = fmaf(q3, a3, xr[i]);
            float m = fmaf(wc0, a0, 1e-6f);   // eps folded in
            m = fmaf(wc1, a1, m);
            m = fmaf(wc2, a2, m);
            mrow[i] = fmaf(wc3, a3, m);
        }
        if (tid == T / CH - 1) {              // A[T-1] -> backward virtual init
            smInit[0] = a0; smInit[1] = a1; smInit[2] = a2; smInit[3] = a3;
        }
    }
    __syncthreads();

    // ===== backward carries: cb = Q16^(31-lane) * Hb_w + Bscan[lane+1] =====
    float cb0, cb1, cb2, cb3;
    {
        float v0 = __shfl_down_sync(ALL, B0, 1);
        float v1 = __shfl_down_sync(ALL, B1, 1);
        float v2 = __shfl_down_sync(ALL, B2, 1);
        float v3 = __shfl_down_sync(ALL, B3, 1);
        float sx0 = (lane < 31) ? v0 : 0.f, sx1 = (lane < 31) ? v1 : 0.f;
        float sx2 = (lane < 31) ? v2 : 0.f, sx3 = (lane < 31) ? v3 : 0.f;
        float H0 = smInit[0], H1 = smInit[1], H2 = smInit[2], H3 = smInit[3];
#pragma unroll
        for (int j = NW - 1; j >= 1; --j) {
            if (j > w) {
                H0 = fmaf(P512_0, H0, smB[j][0]);
                H1 = fmaf(P512_1, H1, smB[j][1]);
                H2 = fmaf(P512_2, H2, smB[j][2]);
                H3 = fmaf(P512_3, H3, smB[j][3]);
            }
        }
        cb0 = fmaf(Qlb0, H0, sx0);
        cb1 = fmaf(Qlb1, H1, sx1);
        cb2 = fmaf(Qlb2, H2, sx2);
        cb3 = fmaf(Qlb3, H3, sx3);
    }

    // ===== bwd pass2 (G chains on x) + final mix + PCEN epilogue + stores =====
    {
        const float* mrow = smM + tid * MPAD;
        float gg0 = cb0, gg1 = cb1, gg2 = cb2, gg3 = cb3;
        float* outp = out + base + tid * CH;
#pragma unroll
        for (int jg = CH / 4 - 1; jg >= 0; --jg) {
            float o0, o1, o2, o3;
#pragma unroll
            for (int ii = 3; ii >= 0; --ii) {
                const int i = 4 * jg + ii;
                gg0 = fmaf(q0, gg0, xr[i]);
                gg1 = fmaf(q1, gg1, xr[i]);
                gg2 = fmaf(q2, gg2, xr[i]);
                gg3 = fmaf(q3, gg3, xr[i]);
                float M = fmaf(nwcx, xr[i], mrow[i]);    // Mpart - Σwc*x + Σwc*G
                M = fmaf(wc0, gg0, M);
                M = fmaf(wc1, gg1, M);
                M = fmaf(wc2, gg2, M);
                M = fmaf(wc3, gg3, M);
                float Mp = ex2_(fmaf(nalpha, lg2_(M), c2));   // (M+eps)^(-a)/delta
                float u  = fmaf(xr[i], Mp, 1.0f);
                float o  = fmaf(dr, ex2_(rr * lg2_(u)), -dr);
                if (ii == 0) o0 = o; else if (ii == 1) o1 = o;
                else if (ii == 2) o2 = o; else o3 = o;
            }
            reinterpret_cast<float4*>(outp)[jg] = make_float4(o0, o1, o2, o3);
        }
    }
}

extern "C" void kernel_launch(void* const* d_in, const int* in_sizes, int n_in,
                              void* d_out, int out_size)
{
    const float* x   = (const float*)d_in[0];
    const float* isa = (const float*)d_in[1];
    const float* ldl = (const float*)d_in[2];
    const float* isr = (const float*)d_in[3];
    const float* zks = (const float*)d_in[4];
    float* out = (float*)d_out;

    const int P    = in_sizes[1];                 // 4
    const int F    = in_sizes[4] / (P * 4);       // 128 (z_ks is [P,K,F], K=4)
    const int rows = in_sizes[0] / 2048;          // B*P*F = 8192

    pcen_kernel<<<rows, 128>>>(x, isa, ldl, isr, zks, out, P, F);
}